// round 10
// baseline (speedup 1.0000x reference)
#include <cuda_runtime.h>
#include <cuda_bf16.h>
#include <cstdint>

#define BB 8
#define CC 64
#define NN 4096
#define KTOP 20
#define OO 64
#define EPSV 1e-5f
#define SLOPE 0.2f
#define TI 64
#define TJ 64
#define NTILES (NN / TJ)
#define NTHR 256
#define PSTR 68
#define NCAND 96            // 4 slices x 24
#define LSZ 24              // per-thread list size (4 groups x 6)

// ---------------- device scratch (no allocation allowed) ----------------
__device__ float g_xt[BB * NN * CC];      // fp32 transposed x: [b][n][c]
__device__ uint4 g_hib[BB * NN * 8];      // bf16 hi part, 64 per point (8 uint4)
__device__ __align__(16) float g_hxx[BB * NN];  // 0.5 * ||x||^2
__device__ int   g_cand[BB * NN * NCAND]; // pass-1 candidate union
__device__ int   g_idx[BB * NN * KTOP];
__device__ float g_A[BB * NN * OO];
__device__ float g_V[BB * NN * OO];

// ---------------- smem layout (bytes) ----------------
#define OFF_A    0                         // 64 x 128B hi, swizzled
#define OFF_B0   8192
#define OFF_B1   16384
#define OFF_PDS  24576                     // [64 cols][68] fp32 keys
#define OFF_HXT  41984                     // 2 x 64 fp32 per-tile hxx (double buf)
#define OFF_HV   42496                     // 24 x 256 fp32 lists
#define OFF_HIDX 67072                     // 24 x 256 uint16
#define OFF_GM   79360                     // 4 x 256 fp32 group mins
#define OFF_GP   83456                     // 4 x 256 int group min pos
#define SMEM_TOPK_BYTES 87552

// ---------------- asm helpers ----------------
__device__ __forceinline__ uint32_t smem_u32(const void* p) {
    uint32_t a;
    asm("{ .reg .u64 t; cvta.to.shared.u64 t, %1; cvt.u32.u64 %0, t; }" : "=r"(a) : "l"(p));
    return a;
}
__device__ __forceinline__ void ldsm_x4(uint32_t& r0, uint32_t& r1, uint32_t& r2, uint32_t& r3,
                                        uint32_t addr) {
    asm volatile("ldmatrix.sync.aligned.m8n8.x4.shared.b16 {%0,%1,%2,%3}, [%4];"
                 : "=r"(r0), "=r"(r1), "=r"(r2), "=r"(r3) : "r"(addr));
}
__device__ __forceinline__ void mma16816(float* d, uint32_t a0, uint32_t a1, uint32_t a2,
                                         uint32_t a3, uint32_t b0, uint32_t b1) {
    asm volatile(
        "mma.sync.aligned.m16n8k16.row.col.f32.bf16.bf16.f32 "
        "{%0,%1,%2,%3},{%4,%5,%6,%7},{%8,%9},{%0,%1,%2,%3};"
        : "+f"(d[0]), "+f"(d[1]), "+f"(d[2]), "+f"(d[3])
        : "r"(a0), "r"(a1), "r"(a2), "r"(a3), "r"(b0), "r"(b1));
}
__device__ __forceinline__ void cp16(uint32_t dst, const void* src) {
    asm volatile("cp.async.cg.shared.global [%0], [%1], 16;" :: "r"(dst), "l"(src));
}
#define CP_COMMIT() asm volatile("cp.async.commit_group;" ::: "memory")
#define CP_WAIT0()  asm volatile("cp.async.wait_group 0;" ::: "memory")

// ---------------- kernel P: transpose, hxx, bf16 hi ----------------
__global__ void prep_kernel(const float* __restrict__ x) {
    int gid = blockIdx.x * blockDim.x + threadIdx.x;  // b*N+n
    int b = gid >> 12, n = gid & (NN - 1);
    const float* xp = x + (size_t)b * CC * NN + n;
    float* tp = g_xt + (size_t)gid * CC;
    uint32_t hi2[32];
    float s = 0.f;
#pragma unroll
    for (int c = 0; c < CC; c += 2) {
        float v0 = xp[(size_t)c * NN];
        float v1 = xp[(size_t)(c + 1) * NN];
        s += v0 * v0 + v1 * v1;
        tp[c] = v0; tp[c + 1] = v1;
        __nv_bfloat16 h0 = __float2bfloat16_rn(v0), h1 = __float2bfloat16_rn(v1);
        hi2[c >> 1] = (uint32_t)__bfloat16_as_ushort(h0) | ((uint32_t)__bfloat16_as_ushort(h1) << 16);
    }
#pragma unroll
    for (int q = 0; q < 8; ++q)
        g_hib[(size_t)gid * 8 + q] = make_uint4(hi2[4*q], hi2[4*q+1], hi2[4*q+2], hi2[4*q+3]);
    g_hxx[gid] = 0.5f * s;
}

// ---------------- kernel B (pass 1): hi-only GEMM + per-slice top-24 ----------------
__global__ __launch_bounds__(NTHR, 2) void topk_kernel() {
    extern __shared__ char sm[];
    const uint32_t base = smem_u32(sm);
    const int tid = threadIdx.x;
    const int lane = tid & 31;
    const int wid = tid >> 5;         // 0..7
    const int rg = wid >> 1;          // row group 0..3
    const int cg = wid & 1;           // col group 0..1
    const int b = blockIdx.y;
    const int i0 = blockIdx.x * TI;
    const int bN = b * NN;
    const float NEG_INF = __int_as_float(0xff800000);

    float* pds  = (float*)(sm + OFF_PDS);
    float* hxxt = (float*)(sm + OFF_HXT);
    float* hv   = (float*)(sm + OFF_HV);
    unsigned short* hidx = (unsigned short*)(sm + OFF_HIDX);
    float* gm   = (float*)(sm + OFF_GM);
    int*   gp   = (int*)(sm + OFF_GP);

    // ---- prologue: async-load A tile (hi), B tile 0, hxx tile 0 ----
    for (int l = tid; l < 512; l += NTHR) {              // 64 rows x 8 chunks
        int row = l >> 3, ch = l & 7;
        uint32_t off = (uint32_t)(row * 128 + ch * 16) ^ ((uint32_t)(row & 7) << 4);
        cp16(base + OFF_A + off, &g_hib[(size_t)(bN + i0 + row) * 8 + ch]);
    }
    for (int l = tid; l < 512; l += NTHR) {
        int row = l >> 3, ch = l & 7;
        uint32_t off = (uint32_t)(row * 128 + ch * 16) ^ ((uint32_t)(row & 7) << 4);
        cp16(base + OFF_B0 + off, &g_hib[(size_t)(bN + row) * 8 + ch]);
    }
    if (tid < 16)
        cp16(base + OFF_HXT + tid * 16, (const char*)g_hxx + (size_t)bN * 4 + tid * 16);
    CP_COMMIT();

    // init selection state: per-thread list of 24 (4 groups x 6)
#pragma unroll
    for (int h = 0; h < LSZ; ++h) { hv[h * NTHR + tid] = NEG_INF; hidx[h * NTHR + tid] = 0; }
#pragma unroll
    for (int g = 0; g < 4; ++g) { gm[g * NTHR + tid] = NEG_INF; gp[g * NTHR + tid] = 0; }
    float kth = NEG_INF;
    const int selrow = tid & 63;
    const int selq   = tid >> 6;
    const int lc0    = selq * 16;

    // per-lane ldmatrix address components (128B rows)
    const int r0 = rg * 16 + (lane >> 2);
    const int arow = rg * 16 + (lane & 15);
    const uint32_t aRowOff = (uint32_t)(arow * 128);
    const uint32_t aXor = ((uint32_t)(arow & 7) << 4);
    const uint32_t aLaneK = ((uint32_t)(lane >> 4)) * 16;
    const int nlane = (lane & 7) + ((lane >> 4) & 1) * 8;
    const uint32_t bXor = ((uint32_t)(nlane & 7) << 4);
    const uint32_t bLaneK = ((uint32_t)((lane >> 3) & 1)) * 16;
    const int cq2 = (lane & 3) * 2;

    const uint32_t kOff[4] = {0, 32, 64, 96};   // K=64 hi-only

    CP_WAIT0();
    __syncthreads();

    for (int t = 0; t < NTILES; ++t) {
        const uint32_t sBcur = base + ((t & 1) ? OFF_B1 : OFF_B0);
        const int hb = (t & 1) * 64;
        // ---- prefetch next B tile + its hxx ----
        if (t + 1 < NTILES) {
            const uint32_t sBn = base + (((t + 1) & 1) ? OFF_B1 : OFF_B0);
            const int j0n = (t + 1) * TJ;
            for (int l = tid; l < 512; l += NTHR) {
                int row = l >> 3, ch = l & 7;
                uint32_t off = (uint32_t)(row * 128 + ch * 16) ^ ((uint32_t)(row & 7) << 4);
                cp16(sBn + off, &g_hib[(size_t)(bN + j0n + row) * 8 + ch]);
            }
            if (tid < 16)
                cp16(base + OFF_HXT + (((t + 1) & 1) * 64) * 4 + tid * 16,
                     (const char*)g_hxx + (size_t)(bN + j0n) * 4 + tid * 16);
        }
        CP_COMMIT();

        // ---- MMA: warp computes 16 rows x 32 cols, K=64 ----
        float d[2][2][4];
#pragma unroll
        for (int g = 0; g < 2; ++g)
#pragma unroll
            for (int h = 0; h < 2; ++h)
                d[g][h][0] = d[g][h][1] = d[g][h][2] = d[g][h][3] = 0.f;

#pragma unroll
        for (int c = 0; c < 4; ++c) {
            uint32_t a0, a1, a2, a3;
            ldsm_x4(a0, a1, a2, a3, base + OFF_A + aRowOff + ((kOff[c] + aLaneK) ^ aXor));
#pragma unroll
            for (int g = 0; g < 2; ++g) {
                uint32_t b0, b1, b2, b3;
                uint32_t brow = (uint32_t)(cg * 32 + g * 16 + nlane);
                ldsm_x4(b0, b1, b2, b3, sBcur + brow * 128 + ((kOff[c] + bLaneK) ^ bXor));
                mma16816(d[g][0], a0, a1, a2, a3, b0, b1);
                mma16816(d[g][1], a0, a1, a2, a3, b2, b3);
            }
        }

        // ---- epilogue: subtract hxx_j, stage keys ----
#pragma unroll
        for (int g = 0; g < 2; ++g)
#pragma unroll
            for (int h = 0; h < 2; ++h) {
                const int lc = cg * 32 + g * 16 + h * 8 + cq2;    // 0..63
                const float hx0 = hxxt[hb + lc];
                const float hx1 = hxxt[hb + lc + 1];
                pds[lc * PSTR + r0]           = d[g][h][0] - hx0;
                pds[(lc + 1) * PSTR + r0]     = d[g][h][1] - hx1;
                pds[lc * PSTR + r0 + 8]       = d[g][h][2] - hx0;
                pds[(lc + 1) * PSTR + r0 + 8] = d[g][h][3] - hx1;
            }
        __syncthreads();

        // ---- scan: 4 threads per row, 16 cols each; top-24 list ----
        {
            const int jg0 = t * TJ + lc0;
            const float* pcol = pds + lc0 * PSTR + selrow;
#pragma unroll 4
            for (int c = 0; c < 16; ++c) {
                float v = pcol[c * PSTR];
                if (v > kth) {
                    float m0 = gm[tid], m1 = gm[NTHR + tid],
                          m2 = gm[2 * NTHR + tid], m3 = gm[3 * NTHR + tid];
                    int g = 0; float mg = m0;
                    if (m1 < mg) { g = 1; mg = m1; }
                    if (m2 < mg) { g = 2; mg = m2; }
                    if (m3 < mg) { g = 3; mg = m3; }
                    int pp = gp[g * NTHR + tid];
                    int slot = (g * 6 + pp) * NTHR + tid;
                    hv[slot] = v;
                    hidx[slot] = (unsigned short)(jg0 + c);
                    float nv = v; int np = pp;
#pragma unroll
                    for (int q = 0; q < 6; ++q) {
                        float w = hv[(g * 6 + q) * NTHR + tid];
                        if (w < nv) { nv = w; np = q; }
                    }
                    gm[g * NTHR + tid] = nv;
                    gp[g * NTHR + tid] = np;
                    if (g == 0) m0 = nv; else if (g == 1) m1 = nv;
                    else if (g == 2) m2 = nv; else m3 = nv;
                    kth = fminf(fminf(m0, m1), fminf(m2, m3));
                }
            }
        }
        CP_WAIT0();
        __syncthreads();
    }

    // ---- dump candidate union: 4 x 24 per row ----
    {
        const int cb = (bN + i0 + selrow) * NCAND + selq * LSZ;
#pragma unroll
        for (int s = 0; s < LSZ; ++s)
            g_cand[cb + s] = (int)hidx[s * NTHR + tid];
    }
}

// ---------------- kernel R (pass 2): exact fp32 rescore of 96 candidates ----------------
__global__ __launch_bounds__(256) void rescore_kernel() {
    __shared__ float xi[8][CC];
    const int tid = threadIdx.x, lane = tid & 31, w = tid >> 5;
    const int b = blockIdx.y, bN = b * NN;
    const int row = blockIdx.x * 8 + w;
    const int grow = bN + row;
    const float NEG_INF = __int_as_float(0xff800000);

    if (lane < 16)
        ((float4*)xi[w])[lane] = ((const float4*)(g_xt + (size_t)grow * CC))[lane];
    __syncwarp();

    float key[3]; int cidx[3];
#pragma unroll
    for (int t = 0; t < 3; ++t) {
        int j = g_cand[(size_t)grow * NCAND + lane * 3 + t];
        cidx[t] = j;
        const float4* xj = (const float4*)(g_xt + (size_t)(bN + j) * CC);
        float dot = 0.f;
#pragma unroll
        for (int q = 0; q < 16; ++q) {
            float4 a = ((const float4*)xi[w])[q];
            float4 v = xj[q];
            dot += a.x * v.x + a.y * v.y + a.z * v.z + a.w * v.w;
        }
        key[t] = dot - g_hxx[bN + j];
    }

    const int obase = grow * KTOP;
    for (int k = 0; k < KTOP; ++k) {
        float lm = key[0]; int ls = 0;
        if (key[1] > lm) { lm = key[1]; ls = 1; }
        if (key[2] > lm) { lm = key[2]; ls = 2; }
        float bv = lm; int bl = lane;
#pragma unroll
        for (int off = 16; off; off >>= 1) {
            float ov = __shfl_down_sync(0xffffffffu, bv, off);
            int ol = __shfl_down_sync(0xffffffffu, bl, off);
            if (ov > bv) { bv = ov; bl = ol; }
        }
        bl = __shfl_sync(0xffffffffu, bl, 0);
        if (lane == bl) {
            g_idx[obase + k] = cidx[ls];
            key[ls] = NEG_INF;
        }
    }
}

// ---------------- kernel C: per-point GEMMs with BN folded in ----------------
__global__ void feat_kernel(const float* __restrict__ W,
                            const float* __restrict__ gamma,
                            const float* __restrict__ beta,
                            const float* __restrict__ rmean,
                            const float* __restrict__ rvar) {
    __shared__ float W1s[CC * OO];
    __shared__ float Wds[CC * OO];
    __shared__ float xts[16 * CC];
    const int tid = threadIdx.x;
    const int b = blockIdx.y;
    const int j0 = blockIdx.x * 16;

    for (int l = tid; l < CC * OO; l += 256) {
        int c = l >> 6, o = l & 63;
        float w1 = W[o * (2 * CC) + c];
        W1s[c * OO + o] = w1;
        Wds[c * OO + o] = W[o * (2 * CC) + CC + c] - w1;
    }
    for (int l = tid; l < 16 * CC; l += 256) {
        xts[l] = g_xt[(size_t)(b * NN + j0 + (l >> 6)) * CC + (l & 63)];
    }
    __syncthreads();

    const int o4 = tid & 15;
    const int pt = tid >> 4;
    const float* xp = xts + pt * CC;
    float4 a1 = {0, 0, 0, 0}, ad = {0, 0, 0, 0};
#pragma unroll 8
    for (int c = 0; c < CC; ++c) {
        float x = xp[c];
        float4 w1 = ((const float4*)W1s)[c * 16 + o4];
        float4 wd = ((const float4*)Wds)[c * 16 + o4];
        a1.x += x * w1.x; a1.y += x * w1.y; a1.z += x * w1.z; a1.w += x * w1.w;
        ad.x += x * wd.x; ad.y += x * wd.y; ad.z += x * wd.z; ad.w += x * wd.w;
    }
    const int o = o4 * 4;
    float4 g  = *(const float4*)(gamma + o);
    float4 be = *(const float4*)(beta + o);
    float4 mu = *(const float4*)(rmean + o);
    float4 va = *(const float4*)(rvar + o);
    float4 inv, A4, V4;
    inv.x = g.x * rsqrtf(va.x + EPSV);
    inv.y = g.y * rsqrtf(va.y + EPSV);
    inv.z = g.z * rsqrtf(va.z + EPSV);
    inv.w = g.w * rsqrtf(va.w + EPSV);
    A4.x = inv.x * a1.x; A4.y = inv.y * a1.y; A4.z = inv.z * a1.z; A4.w = inv.w * a1.w;
    V4.x = inv.x * ad.x + (be.x - mu.x * inv.x);
    V4.y = inv.y * ad.y + (be.y - mu.y * inv.y);
    V4.z = inv.z * ad.z + (be.z - mu.z * inv.z);
    V4.w = inv.w * ad.w + (be.w - mu.w * inv.w);
    size_t basei = (size_t)(b * NN + j0 + pt) * OO + o;
    *(float4*)(g_A + basei) = A4;
    *(float4*)(g_V + basei) = V4;
}

// ---------------- kernel D: gather-max + leaky + transpose-out ----------------
__global__ void outmax_kernel(float* __restrict__ out) {
    __shared__ float res[OO * 33];
    const int tid = threadIdx.x;
    const int b = blockIdx.y;
    const int i0 = blockIdx.x * 32;
    const int w = tid >> 5, lane = tid & 31;
    const float NEG_INF = __int_as_float(0xff800000);

    for (int pp = 0; pp < 4; ++pp) {
        int p = w * 4 + pp;
        int i = i0 + p;
        const int* ix = g_idx + (size_t)(b * NN + i) * KTOP;
        float m0 = NEG_INF, m1 = NEG_INF;
#pragma unroll
        for (int k = 0; k < KTOP; ++k) {
            int j = ix[k];
            const float* ar = g_A + (size_t)(b * NN + j) * OO;
            m0 = fmaxf(m0, ar[lane]);
            m1 = fmaxf(m1, ar[lane + 32]);
        }
        const float* vr = g_V + (size_t)(b * NN + i) * OO;
        float r0 = m0 + vr[lane];
        float r1 = m1 + vr[lane + 32];
        r0 = (r0 >= 0.f) ? r0 : SLOPE * r0;
        r1 = (r1 >= 0.f) ? r1 : SLOPE * r1;
        res[lane * 33 + p] = r0;
        res[(lane + 32) * 33 + p] = r1;
    }
    __syncthreads();
    for (int l = tid; l < OO * 32; l += 256) {
        int o = l >> 5, ii = l & 31;
        out[(size_t)(b * OO + o) * NN + i0 + ii] = res[o * 33 + ii];
    }
}

// ---------------- launch ----------------
extern "C" void kernel_launch(void* const* d_in, const int* in_sizes, int n_in,
                              void* d_out, int out_size) {
    const float* x     = (const float*)d_in[0];
    const float* W     = (const float*)d_in[1];
    const float* gamma = (const float*)d_in[2];
    const float* beta  = (const float*)d_in[3];
    const float* rmean = (const float*)d_in[4];
    const float* rvar  = (const float*)d_in[5];
    float* out = (float*)d_out;

    cudaFuncSetAttribute(topk_kernel, cudaFuncAttributeMaxDynamicSharedMemorySize, SMEM_TOPK_BYTES);

    prep_kernel<<<(BB * NN) / 256, 256>>>(x);
    topk_kernel<<<dim3(NN / TI, BB), NTHR, SMEM_TOPK_BYTES>>>();
    rescore_kernel<<<dim3(NN / 8, BB), 256>>>();
    feat_kernel<<<dim3(NN / 16, BB), 256>>>(W, gamma, beta, rmean, rvar);
    outmax_kernel<<<dim3(NN / 32, BB), 256>>>(out);
}

// round 14
// speedup vs baseline: 1.3265x; 1.3265x over previous
#include <cuda_runtime.h>
#include <cuda_bf16.h>
#include <cstdint>

#define BB 8
#define CC 64
#define NN 4096
#define KTOP 20
#define OO 64
#define EPSV 1e-5f
#define SLOPE 0.2f
#define TI 64
#define TJ 64
#define NTILES (NN / TJ)
#define NTHR 256
#define PSTR 68

// ---------------- device scratch (no allocation allowed) ----------------
__device__ float g_xt[BB * NN * CC];      // fp32 transposed x: [b][n][c]
__device__ uint4 g_hib[BB * NN * 8];      // bf16 hi part, 64 per point (8 uint4)
__device__ uint4 g_lob[BB * NN * 8];      // bf16 lo part
__device__ __align__(16) float g_hxx[BB * NN];  // 0.5 * ||x||^2
__device__ int   g_idx[BB * NN * KTOP];
__device__ float g_A[BB * NN * OO];
__device__ float g_V[BB * NN * OO];

// ---------------- topk smem layout (bytes) ----------------
#define OFF_A    0                         // 64 x 256B (hi|lo), swizzled
#define OFF_B0   16384
#define OFF_B1   32768
#define OFF_PDS  49152                     // [64 cols][68] fp32 keys
#define OFF_HXT  66560                     // 2 x 64 fp32 per-tile hxx (double buf)
#define OFF_HV   67072                     // 20 x 256 fp32 lists
#define OFF_HIDX 87552                     // 20 x 256 uint16
#define OFF_GM   97792                     // 4 x 256 fp32 group mins
#define OFF_GP   101888                    // 4 x 256 int group min pos
#define SMEM_TOPK_BYTES 105984

#define FEAT_SMEM_BYTES 50176              // W1s 16K | Wds 16K | xts 64*68*4

// ---------------- asm helpers ----------------
__device__ __forceinline__ uint32_t smem_u32(const void* p) {
    uint32_t a;
    asm("{ .reg .u64 t; cvta.to.shared.u64 t, %1; cvt.u32.u64 %0, t; }" : "=r"(a) : "l"(p));
    return a;
}
__device__ __forceinline__ void ldsm_x4(uint32_t& r0, uint32_t& r1, uint32_t& r2, uint32_t& r3,
                                        uint32_t addr) {
    asm volatile("ldmatrix.sync.aligned.m8n8.x4.shared.b16 {%0,%1,%2,%3}, [%4];"
                 : "=r"(r0), "=r"(r1), "=r"(r2), "=r"(r3) : "r"(addr));
}
__device__ __forceinline__ void mma16816(float* d, uint32_t a0, uint32_t a1, uint32_t a2,
                                         uint32_t a3, uint32_t b0, uint32_t b1) {
    asm volatile(
        "mma.sync.aligned.m16n8k16.row.col.f32.bf16.bf16.f32 "
        "{%0,%1,%2,%3},{%4,%5,%6,%7},{%8,%9},{%0,%1,%2,%3};"
        : "+f"(d[0]), "+f"(d[1]), "+f"(d[2]), "+f"(d[3])
        : "r"(a0), "r"(a1), "r"(a2), "r"(a3), "r"(b0), "r"(b1));
}
__device__ __forceinline__ void cp16(uint32_t dst, const void* src) {
    asm volatile("cp.async.cg.shared.global [%0], [%1], 16;" :: "r"(dst), "l"(src));
}
#define CP_COMMIT() asm volatile("cp.async.commit_group;" ::: "memory")
#define CP_WAIT0()  asm volatile("cp.async.wait_group 0;" ::: "memory")

// ---------------- kernel P: transpose, hxx, bf16 hi/lo split ----------------
__global__ void prep_kernel(const float* __restrict__ x) {
    int gid = blockIdx.x * blockDim.x + threadIdx.x;  // b*N+n
    int b = gid >> 12, n = gid & (NN - 1);
    const float* xp = x + (size_t)b * CC * NN + n;
    float* tp = g_xt + (size_t)gid * CC;
    uint32_t hi2[32], lo2[32];
    float s = 0.f;
#pragma unroll
    for (int c = 0; c < CC; c += 2) {
        float v0 = xp[(size_t)c * NN];
        float v1 = xp[(size_t)(c + 1) * NN];
        s += v0 * v0 + v1 * v1;
        tp[c] = v0; tp[c + 1] = v1;
        __nv_bfloat16 h0 = __float2bfloat16_rn(v0), h1 = __float2bfloat16_rn(v1);
        float l0 = v0 - __bfloat162float(h0), l1 = v1 - __bfloat162float(h1);
        __nv_bfloat16 L0 = __float2bfloat16_rn(l0), L1 = __float2bfloat16_rn(l1);
        hi2[c >> 1] = (uint32_t)__bfloat16_as_ushort(h0) | ((uint32_t)__bfloat16_as_ushort(h1) << 16);
        lo2[c >> 1] = (uint32_t)__bfloat16_as_ushort(L0) | ((uint32_t)__bfloat16_as_ushort(L1) << 16);
    }
#pragma unroll
    for (int q = 0; q < 8; ++q) {
        g_hib[(size_t)gid * 8 + q] = make_uint4(hi2[4*q], hi2[4*q+1], hi2[4*q+2], hi2[4*q+3]);
        g_lob[(size_t)gid * 8 + q] = make_uint4(lo2[4*q], lo2[4*q+1], lo2[4*q+2], lo2[4*q+3]);
    }
    g_hxx[gid] = 0.5f * s;
}

// ---------------- kernel B: mma.sync distance GEMM (K=192) + streaming top-K ----------------
__global__ __launch_bounds__(NTHR, 2) void topk_kernel() {
    extern __shared__ char sm[];
    const uint32_t base = smem_u32(sm);
    const int tid = threadIdx.x;
    const int lane = tid & 31;
    const int wid = tid >> 5;         // 0..7
    const int rg = wid >> 1;          // row group 0..3  (rows rg*16..+15)
    const int cg = wid & 1;           // col group 0..1  (cols cg*32..+31)
    const int b = blockIdx.y;
    const int i0 = blockIdx.x * TI;
    const int bN = b * NN;
    const float NEG_INF = __int_as_float(0xff800000);

    float* pds  = (float*)(sm + OFF_PDS);
    float* hxxt = (float*)(sm + OFF_HXT);
    float* hv   = (float*)(sm + OFF_HV);
    unsigned short* hidx = (unsigned short*)(sm + OFF_HIDX);
    float* gm   = (float*)(sm + OFF_GM);
    int*   gp   = (int*)(sm + OFF_GP);

    // ---- prologue: async-load A tile, B tile 0, hxx tile 0 ----
    for (int l = tid; l < 1024; l += NTHR) {             // A: 64 rows x 16 chunks
        int row = l >> 4, ch = l & 15;
        const uint4* src = (ch < 8) ? &g_hib[(size_t)(bN + i0 + row) * 8 + ch]
                                    : &g_lob[(size_t)(bN + i0 + row) * 8 + (ch - 8)];
        uint32_t off = (uint32_t)(row * 256 + ch * 16) ^ ((uint32_t)(row & 7) << 4);
        cp16(base + OFF_A + off, src);
    }
    for (int l = tid; l < 1024; l += NTHR) {             // B tile 0
        int row = l >> 4, ch = l & 15;
        const uint4* src = (ch < 8) ? &g_hib[(size_t)(bN + row) * 8 + ch]
                                    : &g_lob[(size_t)(bN + row) * 8 + (ch - 8)];
        uint32_t off = (uint32_t)(row * 256 + ch * 16) ^ ((uint32_t)(row & 7) << 4);
        cp16(base + OFF_B0 + off, src);
    }
    if (tid < 16)                                        // hxx tile 0 (256 B)
        cp16(base + OFF_HXT + tid * 16, (const char*)g_hxx + (size_t)bN * 4 + tid * 16);
    CP_COMMIT();

    // init selection state: 4 lists per row (one per owner thread)
#pragma unroll
    for (int h = 0; h < KTOP; ++h) { hv[h * NTHR + tid] = NEG_INF; hidx[h * NTHR + tid] = 0; }
#pragma unroll
    for (int g = 0; g < 4; ++g) { gm[g * NTHR + tid] = NEG_INF; gp[g * NTHR + tid] = 0; }
    float kth = NEG_INF;
    const int selrow = tid & 63;         // scan row
    const int selq   = tid >> 6;         // 0..3, 16-col slice

    // per-lane ldmatrix address components
    const int r0 = rg * 16 + (lane >> 2);
    const int arow = rg * 16 + (lane & 15);
    const uint32_t aRowOff = (uint32_t)(arow * 256);
    const uint32_t aXor = ((uint32_t)(arow & 7) << 4);
    const uint32_t aLaneK = ((uint32_t)(lane >> 4)) * 16;
    const int nlane = (lane & 7) + ((lane >> 4) & 1) * 8;
    const uint32_t bXor = ((uint32_t)(nlane & 7) << 4);
    const uint32_t bLaneK = ((uint32_t)((lane >> 3) & 1)) * 16;
    const int cq2 = (lane & 3) * 2;

    // k-chunk byte offsets: groups (hi,hi) (lo,hi) (hi,lo)
    const uint32_t kA[12] = {0, 32, 64, 96, 128, 160, 192, 224, 0, 32, 64, 96};
    const uint32_t kB[12] = {0, 32, 64, 96, 0, 32, 64, 96, 128, 160, 192, 224};

    CP_WAIT0();
    __syncthreads();

    for (int t = 0; t < NTILES; ++t) {
        const uint32_t sBcur = base + ((t & 1) ? OFF_B1 : OFF_B0);
        const int hb = (t & 1) * 64;
        // ---- prefetch next B tile + its hxx ----
        if (t + 1 < NTILES) {
            const uint32_t sBn = base + (((t + 1) & 1) ? OFF_B1 : OFF_B0);
            const int j0n = (t + 1) * TJ;
            for (int l = tid; l < 1024; l += NTHR) {
                int row = l >> 4, ch = l & 15;
                const uint4* src = (ch < 8) ? &g_hib[(size_t)(bN + j0n + row) * 8 + ch]
                                            : &g_lob[(size_t)(bN + j0n + row) * 8 + (ch - 8)];
                uint32_t off = (uint32_t)(row * 256 + ch * 16) ^ ((uint32_t)(row & 7) << 4);
                cp16(sBn + off, src);
            }
            if (tid < 16)
                cp16(base + OFF_HXT + (((t + 1) & 1) * 64) * 4 + tid * 16,
                     (const char*)g_hxx + (size_t)(bN + j0n) * 4 + tid * 16);
        }
        CP_COMMIT();

        // ---- MMA: warp computes 16 rows x 32 cols, K=192 effective ----
        float d[2][2][4];
#pragma unroll
        for (int g = 0; g < 2; ++g)
#pragma unroll
            for (int h = 0; h < 2; ++h)
                d[g][h][0] = d[g][h][1] = d[g][h][2] = d[g][h][3] = 0.f;

#pragma unroll
        for (int c = 0; c < 12; ++c) {
            uint32_t a0, a1, a2, a3;
            ldsm_x4(a0, a1, a2, a3, base + OFF_A + aRowOff + ((kA[c] + aLaneK) ^ aXor));
#pragma unroll
            for (int g = 0; g < 2; ++g) {
                uint32_t b0, b1, b2, b3;
                uint32_t brow = (uint32_t)(cg * 32 + g * 16 + nlane);
                ldsm_x4(b0, b1, b2, b3, sBcur + brow * 256 + ((kB[c] + bLaneK) ^ bXor));
                mma16816(d[g][0], a0, a1, a2, a3, b0, b1);
                mma16816(d[g][1], a0, a1, a2, a3, b2, b3);
            }
        }

        // ---- epilogue: subtract hxx_j, stage keys (single phase) ----
#pragma unroll
        for (int g = 0; g < 2; ++g)
#pragma unroll
            for (int h = 0; h < 2; ++h) {
                const int lc = cg * 32 + g * 16 + h * 8 + cq2;    // 0..63
                const float hx0 = hxxt[hb + lc];
                const float hx1 = hxxt[hb + lc + 1];
                pds[lc * PSTR + r0]           = d[g][h][0] - hx0;
                pds[(lc + 1) * PSTR + r0]     = d[g][h][1] - hx1;
                pds[lc * PSTR + r0 + 8]       = d[g][h][2] - hx0;
                pds[(lc + 1) * PSTR + r0 + 8] = d[g][h][3] - hx1;
            }
        __syncthreads();

        // ---- scan: 4 threads per row, 16 cols each ----
        {
            const int lc0 = selq * 16;
            const int jg0 = t * TJ + lc0;
            const float* pcol = pds + lc0 * PSTR + selrow;
#pragma unroll 4
            for (int c = 0; c < 16; ++c) {
                float v = pcol[c * PSTR];
                if (v > kth) {
                    float m0 = gm[tid], m1 = gm[NTHR + tid],
                          m2 = gm[2 * NTHR + tid], m3 = gm[3 * NTHR + tid];
                    int g = 0; float mg = m0;
                    if (m1 < mg) { g = 1; mg = m1; }
                    if (m2 < mg) { g = 2; mg = m2; }
                    if (m3 < mg) { g = 3; mg = m3; }
                    int pp = gp[g * NTHR + tid];
                    int slot = (g * 5 + pp) * NTHR + tid;
                    hv[slot] = v;
                    hidx[slot] = (unsigned short)(jg0 + c);
                    float nv = v; int np = pp;
#pragma unroll
                    for (int q = 0; q < 5; ++q) {
                        float w = hv[(g * 5 + q) * NTHR + tid];
                        if (w < nv) { nv = w; np = q; }
                    }
                    gm[g * NTHR + tid] = nv;
                    gp[g * NTHR + tid] = np;
                    if (g == 0) m0 = nv; else if (g == 1) m1 = nv;
                    else if (g == 2) m2 = nv; else m3 = nv;
                    kth = fminf(fminf(m0, m1), fminf(m2, m3));
                }
            }
        }
        CP_WAIT0();
        __syncthreads();
    }

    // ---- merge 4 lists per row (80 candidates) -> top-20 ----
    if (tid < 64) {
        const int row = tid;
        const int obase = (bN + i0 + row) * KTOP;
        for (int k = 0; k < KTOP; ++k) {
            float best = NEG_INF; int bslot = row;
#pragma unroll
            for (int h = 0; h < KTOP; ++h)
#pragma unroll
                for (int q = 0; q < 4; ++q) {
                    int s = h * NTHR + q * 64 + row;
                    float v = hv[s];
                    if (v > best) { best = v; bslot = s; }
                }
            g_idx[obase + k] = (int)hidx[bslot];
            hv[bslot] = NEG_INF;
        }
    }
}

// ---------------- kernel C: per-point GEMMs, 64 pts/block, 4x4 register blocking ----------------
__global__ __launch_bounds__(256) void feat_kernel(const float* __restrict__ W,
                            const float* __restrict__ gamma,
                            const float* __restrict__ beta,
                            const float* __restrict__ rmean,
                            const float* __restrict__ rvar) {
    extern __shared__ float fsm[];
    float* W1s = fsm;             // [c][o]  (16KB)
    float* Wds = fsm + 4096;      // [c][o]  (16KB)
    float* xts = fsm + 8192;      // [p][c] stride 68 (17.4KB)
    const int tid = threadIdx.x;
    const int b = blockIdx.y;
    const int j0 = blockIdx.x * 64;

    for (int l = tid; l < CC * OO; l += 256) {
        int c = l >> 6, o = l & 63;
        float w1 = W[o * (2 * CC) + c];
        W1s[c * OO + o] = w1;
        Wds[c * OO + o] = W[o * (2 * CC) + CC + c] - w1;
    }
    for (int l = tid; l < 64 * CC; l += 256) {
        int row = l >> 6, c = l & 63;
        xts[row * 68 + c] = g_xt[(size_t)(b * NN + j0 + row) * CC + c];
    }
    __syncthreads();

    const int o4 = tid & 15;      // output quad
    const int pg = tid >> 4;      // point group: points pg*4..+3
    float4 a1[4], ad[4];
#pragma unroll
    for (int i = 0; i < 4; ++i) {
        a1[i] = make_float4(0.f, 0.f, 0.f, 0.f);
        ad[i] = make_float4(0.f, 0.f, 0.f, 0.f);
    }
#pragma unroll 4
    for (int c = 0; c < CC; ++c) {
        float4 w1 = ((const float4*)W1s)[c * 16 + o4];
        float4 wd = ((const float4*)Wds)[c * 16 + o4];
#pragma unroll
        for (int i = 0; i < 4; ++i) {
            float x = xts[(pg * 4 + i) * 68 + c];
            a1[i].x += x * w1.x; a1[i].y += x * w1.y; a1[i].z += x * w1.z; a1[i].w += x * w1.w;
            ad[i].x += x * wd.x; ad[i].y += x * wd.y; ad[i].z += x * wd.z; ad[i].w += x * wd.w;
        }
    }
    const int o = o4 * 4;
    float4 g  = *(const float4*)(gamma + o);
    float4 be = *(const float4*)(beta + o);
    float4 mu = *(const float4*)(rmean + o);
    float4 va = *(const float4*)(rvar + o);
    float4 inv, sh;
    inv.x = g.x * rsqrtf(va.x + EPSV);
    inv.y = g.y * rsqrtf(va.y + EPSV);
    inv.z = g.z * rsqrtf(va.z + EPSV);
    inv.w = g.w * rsqrtf(va.w + EPSV);
    sh.x = be.x - mu.x * inv.x;
    sh.y = be.y - mu.y * inv.y;
    sh.z = be.z - mu.z * inv.z;
    sh.w = be.w - mu.w * inv.w;
#pragma unroll
    for (int i = 0; i < 4; ++i) {
        float4 A4, V4;
        A4.x = inv.x * a1[i].x; A4.y = inv.y * a1[i].y;
        A4.z = inv.z * a1[i].z; A4.w = inv.w * a1[i].w;
        V4.x = inv.x * ad[i].x + sh.x;
        V4.y = inv.y * ad[i].y + sh.y;
        V4.z = inv.z * ad[i].z + sh.z;
        V4.w = inv.w * ad[i].w + sh.w;
        size_t basei = (size_t)(b * NN + j0 + pg * 4 + i) * OO + o;
        *(float4*)(g_A + basei) = A4;
        *(float4*)(g_V + basei) = V4;
    }
}

// ---------------- kernel D: gather-max + leaky + transpose-out ----------------
__global__ void outmax_kernel(float* __restrict__ out) {
    __shared__ float res[OO * 33];
    const int tid = threadIdx.x;
    const int b = blockIdx.y;
    const int i0 = blockIdx.x * 32;
    const int w = tid >> 5, lane = tid & 31;
    const float NEG_INF = __int_as_float(0xff800000);

    for (int pp = 0; pp < 4; ++pp) {
        int p = w * 4 + pp;
        int i = i0 + p;
        const int* ix = g_idx + (size_t)(b * NN + i) * KTOP;
        float m0 = NEG_INF, m1 = NEG_INF;
#pragma unroll
        for (int k = 0; k < KTOP; ++k) {
            int j = ix[k];
            const float* ar = g_A + (size_t)(b * NN + j) * OO;
            m0 = fmaxf(m0, ar[lane]);
            m1 = fmaxf(m1, ar[lane + 32]);
        }
        const float* vr = g_V + (size_t)(b * NN + i) * OO;
        float r0 = m0 + vr[lane];
        float r1 = m1 + vr[lane + 32];
        r0 = (r0 >= 0.f) ? r0 : SLOPE * r0;
        r1 = (r1 >= 0.f) ? r1 : SLOPE * r1;
        res[lane * 33 + p] = r0;
        res[(lane + 32) * 33 + p] = r1;
    }
    __syncthreads();
    for (int l = tid; l < OO * 32; l += 256) {
        int o = l >> 5, ii = l & 31;
        out[(size_t)(b * OO + o) * NN + i0 + ii] = res[o * 33 + ii];
    }
}

// ---------------- launch ----------------
extern "C" void kernel_launch(void* const* d_in, const int* in_sizes, int n_in,
                              void* d_out, int out_size) {
    const float* x     = (const float*)d_in[0];
    const float* W     = (const float*)d_in[1];
    const float* gamma = (const float*)d_in[2];
    const float* beta  = (const float*)d_in[3];
    const float* rmean = (const float*)d_in[4];
    const float* rvar  = (const float*)d_in[5];
    float* out = (float*)d_out;

    cudaFuncSetAttribute(topk_kernel, cudaFuncAttributeMaxDynamicSharedMemorySize, SMEM_TOPK_BYTES);
    cudaFuncSetAttribute(feat_kernel, cudaFuncAttributeMaxDynamicSharedMemorySize, FEAT_SMEM_BYTES);

    prep_kernel<<<(BB * NN) / 256, 256>>>(x);
    topk_kernel<<<dim3(NN / TI, BB), NTHR, SMEM_TOPK_BYTES>>>();
    feat_kernel<<<dim3(NN / 64, BB), 256, FEAT_SMEM_BYTES>>>(W, gamma, beta, rmean, rvar);
    outmax_kernel<<<dim3(NN / 32, BB), 256>>>(out);
}